// round 1
// baseline (speedup 1.0000x reference)
#include <cuda_runtime.h>
#include <math.h>
#include <float.h>

#define NMAX      26400
#define KTOP      1000
#define CONF      0.001f
#define NMS_THR   0.6f
#define CAP       4096
#define BS        512

// ---------------- scratch (no allocation allowed) ----------------
__device__ float g_boxes[NMAX * 4];
__device__ float g_scores[NMAX];
__device__ int   g_cls[NMAX];

// ---------------- kernel 1: decode, one warp per anchor ----------------
__global__ void __launch_bounds__(256) decode_kernel(
    const float* __restrict__ reg, const float* __restrict__ obj,
    const float* __restrict__ cls, const float* __restrict__ grid,
    const float* __restrict__ anch, const float* __restrict__ strd,
    int N, int C)
{
    int warp = (blockIdx.x * blockDim.x + threadIdx.x) >> 5;
    int lane = threadIdx.x & 31;
    if (warp >= N) return;

    const float* cl = cls + (size_t)warp * C;

    // local max / argmax over this lane's classes (first-occurrence tie-break)
    float lv[8]; int nl = 0;
    float vmax = -FLT_MAX; int amax = 0x7fffffff;
    for (int c = lane; c < C; c += 32) {
        float x = cl[c];
        lv[nl++] = x;
        if (x > vmax) { vmax = x; amax = c; }
    }
    // warp argmax reduce (prefer larger value; on tie, smaller index)
    for (int off = 16; off; off >>= 1) {
        float ov = __shfl_down_sync(0xffffffffu, vmax, off);
        int   oa = __shfl_down_sync(0xffffffffu, amax, off);
        if (ov > vmax || (ov == vmax && oa < amax)) { vmax = ov; amax = oa; }
    }
    vmax = __shfl_sync(0xffffffffu, vmax, 0);
    amax = __shfl_sync(0xffffffffu, amax, 0);

    // sum of exp(l - max)
    float se = 0.f;
    for (int t = 0; t < nl; t++) se += expf(lv[t] - vmax);
    for (int off = 16; off; off >>= 1)
        se += __shfl_down_sync(0xffffffffu, se, off);

    if (lane == 0) {
        float sig_obj = 1.f / (1.f + expf(-obj[warp]));
        float score   = sig_obj * (1.f / se);   // sigmoid(obj) * max softmax
        g_scores[warp] = score;
        g_cls[warp]    = amax;

        float s  = strd[warp];
        float gx = grid[warp * 2 + 0], gy = grid[warp * 2 + 1];
        float aw = anch[warp * 2 + 0], ah = anch[warp * 2 + 1];
        float rx = reg[warp * 4 + 0], ry = reg[warp * 4 + 1];
        float rw = reg[warp * 4 + 2], rh = reg[warp * 4 + 3];

        float cx = (1.f / (1.f + expf(-rx)) + gx) * s;
        float cy = (1.f / (1.f + expf(-ry)) + gy) * s;
        float w  = expf(rw) * aw;
        float h  = expf(rh) * ah;

        float x1 = fminf(fmaxf((cx - 0.5f * w) / 640.0f, 0.f), 1.f);
        float y1 = fminf(fmaxf((cy - 0.5f * h) / 640.0f, 0.f), 1.f);
        float x2 = fminf(fmaxf((cx + 0.5f * w) / 640.0f, 0.f), 1.f);
        float y2 = fminf(fmaxf((cy + 0.5f * h) / 640.0f, 0.f), 1.f);

        g_boxes[warp * 4 + 0] = x1;
        g_boxes[warp * 4 + 1] = y1;
        g_boxes[warp * 4 + 2] = x2;
        g_boxes[warp * 4 + 3] = y2;
    }
}

// ---------------- kernel 2: per-class topK + fill + NMS ----------------
// One block per class. Shared memory reused across phases:
//  buf[0    .. 4096) : candidate scores  -> final slot vals  (first 1000)
//  buf[4096 .. 8192) : candidate indices -> final slot idx   (first 1000 words)
//  After sort, free sub-regions are reused for box data:
//  bx1 @1024, by1 @2048, bx2 @3072, by2 @5120, area @6144, keep @7168
__global__ void __launch_bounds__(BS) class_kernel(
    float* __restrict__ out_boxes, float* __restrict__ out_scores,
    float* __restrict__ out_keep, int N)
{
    __shared__ float buf[8192];
    __shared__ int s_cnt, s_run, s_wsum[BS / 32];

    float* sc   = buf;
    int*   sidx = (int*)(buf + 4096);
    float* bx1  = buf + 1024;
    float* by1  = buf + 2048;
    float* bx2  = buf + 3072;
    float* by2  = buf + 5120;
    float* sar  = buf + 6144;
    int*   skeep = (int*)(buf + 7168);

    const int cls = blockIdx.x;
    const int tid = threadIdx.x;
    const int wid = tid >> 5;
    const int lane = tid & 31;

    if (tid == 0) { s_cnt = 0; s_run = 0; }
    __syncthreads();

    // ---- Phase A: collect candidates ----
    for (int a = tid; a < N; a += BS) {
        if (g_cls[a] == cls && g_scores[a] >= CONF) {
            int p = atomicAdd(&s_cnt, 1);
            if (p < CAP) { sc[p] = g_scores[a]; sidx[p] = a; }
        }
    }
    __syncthreads();
    int cnt = min(s_cnt, CAP);

    // ---- Phase B: bitonic sort (score desc, idx asc) ----
    int M = 2; while (M < cnt) M <<= 1;
    for (int i = cnt + tid; i < M; i += BS) { sc[i] = -FLT_MAX; sidx[i] = 0x7fffffff; }
    __syncthreads();

    for (int k = 2; k <= M; k <<= 1) {
        for (int j = k >> 1; j > 0; j >>= 1) {
            for (int i = tid; i < M; i += BS) {
                int l = i ^ j;
                if (l > i) {
                    float si = sc[i], sl = sc[l];
                    int   ii = sidx[i], il = sidx[l];
                    // lPrec: element at l should come before element at i
                    bool lPrec = (sl > si) || (sl == si && il < ii);
                    bool dir   = ((i & k) == 0);
                    if (lPrec == dir) {
                        sc[i] = sl; sc[l] = si;
                        sidx[i] = il; sidx[l] = ii;
                    }
                }
            }
            __syncthreads();
        }
    }

    // ---- Phase C: fill remaining slots with lowest-index non-candidates ----
    const int V = min(cnt, KTOP);
    const int need = KTOP - V;
    if (need > 0) {
        for (int base = 0;; base += BS) {
            int a = base + tid;
            int flag = 0;
            if (a < N) flag = !(g_cls[a] == cls && g_scores[a] >= CONF);
            unsigned m = __ballot_sync(0xffffffffu, flag);
            int wpos = __popc(m & ((1u << lane) - 1u));
            if (lane == 0) s_wsum[wid] = __popc(m);
            __syncthreads();
            int off = 0, tot = 0;
            #pragma unroll
            for (int w = 0; w < BS / 32; w++) {
                if (w < wid) off += s_wsum[w];
                tot += s_wsum[w];
            }
            int run = s_run;
            int pos = run + off + wpos;
            if (flag && pos < need) { sc[V + pos] = -1.0f; sidx[V + pos] = a; }
            __syncthreads();
            if (tid == 0) s_run = run + tot;
            __syncthreads();
            if (run + tot >= need) break;
            if (base + BS >= N) break;
        }
    }
    __syncthreads();

    // ---- Phase D: gather boxes, write boxes_out, init keep/area ----
    for (int k = tid; k < KTOP; k += BS) {
        int a = sidx[k];
        float x1 = g_boxes[a * 4 + 0];
        float y1 = g_boxes[a * 4 + 1];
        float x2 = g_boxes[a * 4 + 2];
        float y2 = g_boxes[a * 4 + 3];
        bx1[k] = x1; by1[k] = y1; bx2[k] = x2; by2[k] = y2;
        sar[k] = (x2 - x1) * (y2 - y1);
        skeep[k] = (sc[k] > 0.0f) ? 1 : 0;
        float* ob = out_boxes + ((size_t)cls * KTOP + k) * 4;
        ob[0] = x1; ob[1] = y1; ob[2] = x2; ob[3] = y2;
    }
    __syncthreads();

    // ---- Phase E: greedy NMS over valid prefix ----
    for (int i = 0; i < V; i++) {
        if (skeep[i]) {
            float xi1 = bx1[i], yi1 = by1[i], xi2 = bx2[i], yi2 = by2[i];
            float ai = sar[i];
            for (int j = i + 1 + tid; j < V; j += BS) {
                if (skeep[j]) {
                    float xx1 = fmaxf(xi1, bx1[j]);
                    float yy1 = fmaxf(yi1, by1[j]);
                    float xx2 = fminf(xi2, bx2[j]);
                    float yy2 = fminf(yi2, by2[j]);
                    float w = fmaxf(1e-28f, xx2 - xx1);
                    float h = fmaxf(1e-28f, yy2 - yy1);
                    float inter = w * h;
                    float iou = inter / (ai + sar[j] - inter + 1e-14f);
                    if (iou > NMS_THR) skeep[j] = 0;
                }
            }
        }
        __syncthreads();
    }

    // ---- Phase F: write scores * keep, keep ----
    for (int k = tid; k < KTOP; k += BS) {
        float kp = skeep[k] ? 1.0f : 0.0f;
        out_scores[(size_t)cls * KTOP + k] = sc[k] * kp;
        out_keep[(size_t)cls * KTOP + k]   = kp;
    }
}

// ---------------- launch ----------------
extern "C" void kernel_launch(void* const* d_in, const int* in_sizes, int n_in,
                              void* d_out, int out_size)
{
    const float* reg  = (const float*)d_in[0];
    const float* obj  = (const float*)d_in[1];
    const float* cls  = (const float*)d_in[2];
    const float* grid = (const float*)d_in[3];
    const float* anch = (const float*)d_in[4];
    const float* strd = (const float*)d_in[5];

    int N = in_sizes[0] / 4;
    int C = in_sizes[2] / N;

    float* out = (float*)d_out;
    float* out_boxes  = out;                         // [C, K, 4]
    float* out_scores = out + (size_t)C * KTOP * 4;  // [C, K]
    float* out_keep   = out + (size_t)C * KTOP * 5;  // [C, K]

    // decode: 8 warps per block, 1 warp per anchor
    int blocks = (N + 7) / 8;
    decode_kernel<<<blocks, 256>>>(reg, obj, cls, grid, anch, strd, N, C);

    // per-class selection + NMS: one block per class
    class_kernel<<<C, BS>>>(out_boxes, out_scores, out_keep, N);
}

// round 2
// speedup vs baseline: 1.9315x; 1.9315x over previous
#include <cuda_runtime.h>
#include <math.h>
#include <float.h>

#define NMAX      26400
#define KTOP      1000
#define CONF      0.001f
#define NMS_THR   0.6f
#define CAP       2048
#define BS        512
#define MW        13          // mask words per row (covers V <= 416)
#define VMAXF     408         // fast-path limit (smem budget)

// ---------------- scratch (no allocation allowed) ----------------
__device__ float  g_boxes[NMAX * 4];
__device__ float2 g_pack[NMAX];     // {score, bitcast(cls)}

// ---------------- kernel 1: decode, one warp per anchor ----------------
__global__ void __launch_bounds__(256) decode_kernel(
    const float* __restrict__ reg, const float* __restrict__ obj,
    const float* __restrict__ cls, const float* __restrict__ grid,
    const float* __restrict__ anch, const float* __restrict__ strd,
    int N, int C)
{
    int warp = (blockIdx.x * blockDim.x + threadIdx.x) >> 5;
    int lane = threadIdx.x & 31;
    if (warp >= N) return;

    const float* cl = cls + (size_t)warp * C;

    float lv[8]; int nl = 0;
    float vmax = -FLT_MAX; int amax = 0x7fffffff;
    for (int c = lane; c < C; c += 32) {
        float x = cl[c];
        lv[nl++] = x;
        if (x > vmax) { vmax = x; amax = c; }
    }
    for (int off = 16; off; off >>= 1) {
        float ov = __shfl_down_sync(0xffffffffu, vmax, off);
        int   oa = __shfl_down_sync(0xffffffffu, amax, off);
        if (ov > vmax || (ov == vmax && oa < amax)) { vmax = ov; amax = oa; }
    }
    vmax = __shfl_sync(0xffffffffu, vmax, 0);
    amax = __shfl_sync(0xffffffffu, amax, 0);

    float se = 0.f;
    for (int t = 0; t < nl; t++) se += expf(lv[t] - vmax);
    for (int off = 16; off; off >>= 1)
        se += __shfl_down_sync(0xffffffffu, se, off);

    if (lane == 0) {
        float sig_obj = 1.f / (1.f + expf(-obj[warp]));
        float score   = sig_obj * (1.f / se);
        g_pack[warp] = make_float2(score, __int_as_float(amax));

        float s  = strd[warp];
        float gx = grid[warp * 2 + 0], gy = grid[warp * 2 + 1];
        float aw = anch[warp * 2 + 0], ah = anch[warp * 2 + 1];
        float rx = reg[warp * 4 + 0], ry = reg[warp * 4 + 1];
        float rw = reg[warp * 4 + 2], rh = reg[warp * 4 + 3];

        float cx = (1.f / (1.f + expf(-rx)) + gx) * s;
        float cy = (1.f / (1.f + expf(-ry)) + gy) * s;
        float w  = expf(rw) * aw;
        float h  = expf(rh) * ah;

        float x1 = fminf(fmaxf((cx - 0.5f * w) / 640.0f, 0.f), 1.f);
        float y1 = fminf(fmaxf((cy - 0.5f * h) / 640.0f, 0.f), 1.f);
        float x2 = fminf(fmaxf((cx + 0.5f * w) / 640.0f, 0.f), 1.f);
        float y2 = fminf(fmaxf((cy + 0.5f * h) / 640.0f, 0.f), 1.f);

        g_boxes[warp * 4 + 0] = x1;
        g_boxes[warp * 4 + 1] = y1;
        g_boxes[warp * 4 + 2] = x2;
        g_boxes[warp * 4 + 3] = y2;
    }
}

// ---------------- kernel 2: per-class topK + fill + mask-NMS ----------------
// Static smem layout (buf = 12000 floats = 48000 B):
//  sc    @0     (2048)   candidate scores -> sorted vals
//  sidx  @2048  (2048)   candidate anchor indices
//  bx1   @4096, by1 @4608, bx2 @5120, by2 @5632, sar @6144  (512 each, k < V)
//  mask  @6656  (408*13 = 5304 uint words)   upper-tri suppression bits
//  alive @11960 (16 uint words)              resolved keep bitset
__global__ void __launch_bounds__(BS) class_kernel(
    float* __restrict__ out_boxes, float* __restrict__ out_scores,
    float* __restrict__ out_keep, int N)
{
    __shared__ float buf[12000];
    __shared__ int s_cnt, s_run, s_wsum[BS / 32];

    float*    sc    = buf;
    int*      sidx  = (int*)(buf + 2048);
    float*    bx1   = buf + 4096;
    float*    by1   = buf + 4608;
    float*    bx2   = buf + 5120;
    float*    by2   = buf + 5632;
    float*    sar   = buf + 6144;
    unsigned* maskA = (unsigned*)(buf + 6656);
    unsigned* aliveW = (unsigned*)(buf + 11960);

    const int cls  = blockIdx.x;
    const int tid  = threadIdx.x;
    const int wid  = tid >> 5;
    const int lane = tid & 31;

    if (tid == 0) { s_cnt = 0; s_run = 0; }
    __syncthreads();

    // ---- Phase A: collect candidates (vectorized packed load) ----
    #pragma unroll 4
    for (int a = tid; a < N; a += BS) {
        float2 p = g_pack[a];
        if (__float_as_int(p.y) == cls && p.x >= CONF) {
            int q = atomicAdd(&s_cnt, 1);
            if (q < CAP) { sc[q] = p.x; sidx[q] = a; }
        }
    }
    __syncthreads();
    int cnt = min(s_cnt, CAP);

    // ---- Phase B: bitonic sort (score desc, idx asc) ----
    int M = 2; while (M < cnt) M <<= 1;
    for (int i = cnt + tid; i < M; i += BS) { sc[i] = -FLT_MAX; sidx[i] = 0x7fffffff; }
    __syncthreads();

    for (int k = 2; k <= M; k <<= 1) {
        for (int j = k >> 1; j > 0; j >>= 1) {
            for (int i = tid; i < M; i += BS) {
                int l = i ^ j;
                if (l > i) {
                    float si = sc[i], sl = sc[l];
                    int   ii = sidx[i], il = sidx[l];
                    bool lPrec = (sl > si) || (sl == si && il < ii);
                    bool dir   = ((i & k) == 0);
                    if (lPrec == dir) {
                        sc[i] = sl; sc[l] = si;
                        sidx[i] = il; sidx[l] = ii;
                    }
                }
            }
            __syncthreads();
        }
    }

    // ---- Phase C: fill remaining slots with lowest-index non-candidates ----
    const int V = min(cnt, KTOP);
    const int need = KTOP - V;
    if (need > 0) {
        for (int base = 0;; base += BS) {
            int a = base + tid;
            int flag = 0;
            if (a < N) {
                float2 p = g_pack[a];
                flag = !(__float_as_int(p.y) == cls && p.x >= CONF);
            }
            unsigned m = __ballot_sync(0xffffffffu, flag);
            int wpos = __popc(m & ((1u << lane) - 1u));
            if (lane == 0) s_wsum[wid] = __popc(m);
            __syncthreads();
            int off = 0, tot = 0;
            #pragma unroll
            for (int w = 0; w < BS / 32; w++) {
                if (w < wid) off += s_wsum[w];
                tot += s_wsum[w];
            }
            int run = s_run;
            int pos = run + off + wpos;
            if (flag && pos < need) { sc[V + pos] = -1.0f; sidx[V + pos] = a; }
            __syncthreads();
            if (tid == 0) s_run = run + tot;
            __syncthreads();
            if (run + tot >= need) break;
            if (base + BS >= N) break;
        }
    }
    __syncthreads();

    const bool fast = (V <= VMAXF);

    // ---- Phase D: gather boxes -> out_boxes; stage first V in smem ----
    for (int k = tid; k < KTOP; k += BS) {
        int a = sidx[k];
        float x1 = g_boxes[a * 4 + 0];
        float y1 = g_boxes[a * 4 + 1];
        float x2 = g_boxes[a * 4 + 2];
        float y2 = g_boxes[a * 4 + 3];
        if (fast && k < V) {
            bx1[k] = x1; by1[k] = y1; bx2[k] = x2; by2[k] = y2;
            sar[k] = (x2 - x1) * (y2 - y1);
        }
        float* ob = out_boxes + ((size_t)cls * KTOP + k) * 4;
        ob[0] = x1; ob[1] = y1; ob[2] = x2; ob[3] = y2;
    }
    __syncthreads();

    if (fast) {
        // ---- Phase E (fast): parallel upper-tri IoU mask build, no barriers ----
        int totalW = V * MW;
        for (int p = tid; p < totalW; p += BS) {
            int i = p / MW;
            int w = p - i * MW;
            float xi1 = bx1[i], yi1 = by1[i], xi2 = bx2[i], yi2 = by2[i];
            float ai  = sar[i];
            unsigned word = 0;
            int jbase = w << 5;
            int jend  = min(V, jbase + 32);
            for (int j = max(jbase, i + 1); j < jend; j++) {
                float xx1 = fmaxf(xi1, bx1[j]);
                float yy1 = fmaxf(yi1, by1[j]);
                float xx2 = fminf(xi2, bx2[j]);
                float yy2 = fminf(yi2, by2[j]);
                float ww = fmaxf(1e-28f, xx2 - xx1);
                float hh = fmaxf(1e-28f, yy2 - yy1);
                float inter = ww * hh;
                float iou = inter / (ai + sar[j] - inter + 1e-14f);
                if (iou > NMS_THR) word |= 1u << (j - jbase);
            }
            maskA[p] = word;
        }
        __syncthreads();

        // ---- resolve: warp 0, alive bits in registers, skip dead rows ----
        if (tid < 32) {
            unsigned alive = 0;
            if (lane < MW) {
                int lo = lane << 5;
                if (lo + 32 <= V)      alive = 0xffffffffu;
                else if (lo < V)       alive = (1u << (V - lo)) - 1u;
            }
            for (int w0 = 0; (w0 << 5) < V; w0++) {
                unsigned done = 0;
                while (true) {
                    unsigned aw = __shfl_sync(0xffffffffu, alive, w0) & ~done;
                    if (!aw) break;
                    int b = __ffs(aw) - 1;
                    int i = (w0 << 5) + b;
                    done |= 1u << b;
                    unsigned row = (lane < MW) ? maskA[i * MW + lane] : 0u;
                    alive &= ~row;
                }
            }
            if (lane < 16) aliveW[lane] = (lane < MW) ? alive : 0u;
        }
        __syncthreads();

        // ---- Phase F: outputs ----
        for (int k = tid; k < KTOP; k += BS) {
            float kp = 0.f;
            if (k < V) kp = ((aliveW[k >> 5] >> (k & 31)) & 1u) ? 1.f : 0.f;
            out_scores[(size_t)cls * KTOP + k] = sc[k] * kp;
            out_keep[(size_t)cls * KTOP + k]   = kp;
        }
    } else {
        // ---- Phase E (fallback, V > VMAXF): barriered greedy NMS ----
        int* kfb = (int*)maskA;   // reuse mask region (>= KTOP ints)
        for (int k = tid; k < V; k += BS) kfb[k] = 1;
        __syncthreads();
        for (int i = 0; i < V; i++) {
            if (kfb[i]) {
                int ia = sidx[i];
                float xi1 = g_boxes[ia * 4 + 0], yi1 = g_boxes[ia * 4 + 1];
                float xi2 = g_boxes[ia * 4 + 2], yi2 = g_boxes[ia * 4 + 3];
                float ai = (xi2 - xi1) * (yi2 - yi1);
                for (int j = i + 1 + tid; j < V; j += BS) {
                    if (kfb[j]) {
                        int ja = sidx[j];
                        float x1 = g_boxes[ja * 4 + 0], y1 = g_boxes[ja * 4 + 1];
                        float x2 = g_boxes[ja * 4 + 2], y2 = g_boxes[ja * 4 + 3];
                        float aj = (x2 - x1) * (y2 - y1);
                        float xx1 = fmaxf(xi1, x1);
                        float yy1 = fmaxf(yi1, y1);
                        float xx2 = fminf(xi2, x2);
                        float yy2 = fminf(yi2, y2);
                        float ww = fmaxf(1e-28f, xx2 - xx1);
                        float hh = fmaxf(1e-28f, yy2 - yy1);
                        float inter = ww * hh;
                        float iou = inter / (ai + aj - inter + 1e-14f);
                        if (iou > NMS_THR) kfb[j] = 0;
                    }
                }
            }
            __syncthreads();
        }
        for (int k = tid; k < KTOP; k += BS) {
            float kp = (k < V && kfb[k]) ? 1.f : 0.f;
            out_scores[(size_t)cls * KTOP + k] = sc[k] * kp;
            out_keep[(size_t)cls * KTOP + k]   = kp;
        }
    }
}

// ---------------- launch ----------------
extern "C" void kernel_launch(void* const* d_in, const int* in_sizes, int n_in,
                              void* d_out, int out_size)
{
    const float* reg  = (const float*)d_in[0];
    const float* obj  = (const float*)d_in[1];
    const float* cls  = (const float*)d_in[2];
    const float* grid = (const float*)d_in[3];
    const float* anch = (const float*)d_in[4];
    const float* strd = (const float*)d_in[5];

    int N = in_sizes[0] / 4;
    int C = in_sizes[2] / N;

    float* out = (float*)d_out;
    float* out_boxes  = out;                         // [C, K, 4]
    float* out_scores = out + (size_t)C * KTOP * 4;  // [C, K]
    float* out_keep   = out + (size_t)C * KTOP * 5;  // [C, K]

    int blocks = (N + 7) / 8;
    decode_kernel<<<blocks, 256>>>(reg, obj, cls, grid, anch, strd, N, C);
    class_kernel<<<C, BS>>>(out_boxes, out_scores, out_keep, N);
}

// round 4
// speedup vs baseline: 2.7593x; 1.4286x over previous
#include <cuda_runtime.h>
#include <math.h>
#include <float.h>

#define NMAX      26400
#define KTOP      1000
#define CONF      0.001f
#define NMS_THR   0.6f
#define CAP       2048
#define BS        512
#define MW        13          // mask words per row (covers V <= 416)
#define VMAXF     408         // fast-path limit (smem budget)

// ---------------- scratch (no allocation allowed) ----------------
__device__ float  g_boxes[NMAX * 4];
__device__ float2 g_pack[NMAX];     // {score, bitcast(cls)}

// ---------------- kernel 1: decode, one warp per anchor ----------------
// Class row is 80 floats = 320 B, 16B-aligned: lanes 0..19 each load one float4.
__global__ void __launch_bounds__(256) decode_kernel(
    const float* __restrict__ reg, const float* __restrict__ obj,
    const float* __restrict__ cls, const float* __restrict__ grid,
    const float* __restrict__ anch, const float* __restrict__ strd,
    int N, int C)
{
    int warp = (blockIdx.x * blockDim.x + threadIdx.x) >> 5;
    int lane = threadIdx.x & 31;
    if (warp >= N) return;

    float vmax = -FLT_MAX; int amax = 0x7fffffff;
    float v0 = 0.f, v1 = 0.f, v2 = 0.f, v3 = 0.f;
    int nq = (C + 3) >> 2;            // quads per row (20 for C=80)
    bool has = lane < nq;
    if (has) {
        const float4* cl4 = (const float4*)(cls + (size_t)warp * C);
        float4 q = cl4[lane];
        v0 = q.x; v1 = q.y; v2 = q.z; v3 = q.w;
        int base = lane << 2;
        // first-occurrence max within the quad (strict >)
        vmax = v0; amax = base;
        if (v1 > vmax) { vmax = v1; amax = base + 1; }
        if (v2 > vmax) { vmax = v2; amax = base + 2; }
        if (v3 > vmax) { vmax = v3; amax = base + 3; }
    }
    // warp argmax reduce (prefer larger value; on tie, smaller index)
    for (int off = 16; off; off >>= 1) {
        float ov = __shfl_down_sync(0xffffffffu, vmax, off);
        int   oa = __shfl_down_sync(0xffffffffu, amax, off);
        if (ov > vmax || (ov == vmax && oa < amax)) { vmax = ov; amax = oa; }
    }
    vmax = __shfl_sync(0xffffffffu, vmax, 0);
    amax = __shfl_sync(0xffffffffu, amax, 0);

    float se = 0.f;
    if (has) {
        se = expf(v0 - vmax) + expf(v1 - vmax)
           + expf(v2 - vmax) + expf(v3 - vmax);
    }
    for (int off = 16; off; off >>= 1)
        se += __shfl_down_sync(0xffffffffu, se, off);

    if (lane == 0) {
        float sig_obj = 1.f / (1.f + expf(-obj[warp]));
        float score   = sig_obj * (1.f / se);
        g_pack[warp] = make_float2(score, __int_as_float(amax));

        float s  = strd[warp];
        float gx = grid[warp * 2 + 0], gy = grid[warp * 2 + 1];
        float aw = anch[warp * 2 + 0], ah = anch[warp * 2 + 1];
        float rx = reg[warp * 4 + 0], ry = reg[warp * 4 + 1];
        float rw = reg[warp * 4 + 2], rh = reg[warp * 4 + 3];

        float cx = (1.f / (1.f + expf(-rx)) + gx) * s;
        float cy = (1.f / (1.f + expf(-ry)) + gy) * s;
        float w  = expf(rw) * aw;
        float h  = expf(rh) * ah;

        float x1 = fminf(fmaxf((cx - 0.5f * w) / 640.0f, 0.f), 1.f);
        float y1 = fminf(fmaxf((cy - 0.5f * h) / 640.0f, 0.f), 1.f);
        float x2 = fminf(fmaxf((cx + 0.5f * w) / 640.0f, 0.f), 1.f);
        float y2 = fminf(fmaxf((cy + 0.5f * h) / 640.0f, 0.f), 1.f);

        g_boxes[warp * 4 + 0] = x1;
        g_boxes[warp * 4 + 1] = y1;
        g_boxes[warp * 4 + 2] = x2;
        g_boxes[warp * 4 + 3] = y2;
    }
}

// ---------------- kernel 2: per-class topK + fill + mask-NMS ----------------
__global__ void __launch_bounds__(BS) class_kernel(
    float* __restrict__ out_boxes, float* __restrict__ out_scores,
    float* __restrict__ out_keep, int N)
{
    __shared__ float buf[12000];
    __shared__ int s_cnt, s_run, s_wsum[BS / 32];

    float*    sc    = buf;
    int*      sidx  = (int*)(buf + 2048);
    float*    bx1   = buf + 4096;
    float*    by1   = buf + 4608;
    float*    bx2   = buf + 5120;
    float*    by2   = buf + 5632;
    float*    sar   = buf + 6144;
    unsigned* maskA = (unsigned*)(buf + 6656);
    unsigned* aliveW = (unsigned*)(buf + 11960);

    const int cls  = blockIdx.x;
    const int tid  = threadIdx.x;
    const int wid  = tid >> 5;
    const int lane = tid & 31;

    if (tid == 0) { s_cnt = 0; s_run = 0; }
    __syncthreads();

    // ---- Phase A: collect candidates ----
    #pragma unroll 4
    for (int a = tid; a < N; a += BS) {
        float2 p = g_pack[a];
        if (__float_as_int(p.y) == cls && p.x >= CONF) {
            int q = atomicAdd(&s_cnt, 1);
            if (q < CAP) { sc[q] = p.x; sidx[q] = a; }
        }
    }
    __syncthreads();
    int cnt = min(s_cnt, CAP);

    // ---- Phase B: bitonic sort (score desc, idx asc) ----
    int M = 2; while (M < cnt) M <<= 1;
    for (int i = cnt + tid; i < M; i += BS) { sc[i] = -FLT_MAX; sidx[i] = 0x7fffffff; }
    __syncthreads();

    for (int k = 2; k <= M; k <<= 1) {
        for (int j = k >> 1; j > 0; j >>= 1) {
            for (int i = tid; i < M; i += BS) {
                int l = i ^ j;
                if (l > i) {
                    float si = sc[i], sl = sc[l];
                    int   ii = sidx[i], il = sidx[l];
                    bool lPrec = (sl > si) || (sl == si && il < ii);
                    bool dir   = ((i & k) == 0);
                    if (lPrec == dir) {
                        sc[i] = sl; sc[l] = si;
                        sidx[i] = il; sidx[l] = ii;
                    }
                }
            }
            __syncthreads();
        }
    }

    // ---- Phase C: fill remaining slots with lowest-index non-candidates ----
    const int V = min(cnt, KTOP);
    const int need = KTOP - V;
    if (need > 0) {
        for (int base = 0;; base += BS) {
            int a = base + tid;
            int flag = 0;
            if (a < N) {
                float2 p = g_pack[a];
                flag = !(__float_as_int(p.y) == cls && p.x >= CONF);
            }
            unsigned m = __ballot_sync(0xffffffffu, flag);
            int wpos = __popc(m & ((1u << lane) - 1u));
            if (lane == 0) s_wsum[wid] = __popc(m);
            __syncthreads();
            int off = 0, tot = 0;
            #pragma unroll
            for (int w = 0; w < BS / 32; w++) {
                if (w < wid) off += s_wsum[w];
                tot += s_wsum[w];
            }
            int run = s_run;
            int pos = run + off + wpos;
            if (flag && pos < need) { sc[V + pos] = -1.0f; sidx[V + pos] = a; }
            __syncthreads();
            if (tid == 0) s_run = run + tot;
            __syncthreads();
            if (run + tot >= need) break;
            if (base + BS >= N) break;
        }
    }
    __syncthreads();

    const bool fast = (V <= VMAXF);

    // ---- Phase D: gather boxes -> out_boxes; stage first V in smem ----
    for (int k = tid; k < KTOP; k += BS) {
        int a = sidx[k];
        float x1 = g_boxes[a * 4 + 0];
        float y1 = g_boxes[a * 4 + 1];
        float x2 = g_boxes[a * 4 + 2];
        float y2 = g_boxes[a * 4 + 3];
        if (fast && k < V) {
            bx1[k] = x1; by1[k] = y1; bx2[k] = x2; by2[k] = y2;
            sar[k] = (x2 - x1) * (y2 - y1);
        }
        float* ob = out_boxes + ((size_t)cls * KTOP + k) * 4;
        ob[0] = x1; ob[1] = y1; ob[2] = x2; ob[3] = y2;
    }
    __syncthreads();

    if (fast) {
        // ---- Phase E: warp-cooperative tiled IoU mask build ----
        // A warp owns a 32x32 tile: lane caches box j in registers (bank=lane,
        // conflict-free burst); row-i loads are warp-uniform broadcasts (free);
        // the row's 32 suppression bits come from one ballot.
        const int nt = (V + 31) >> 5;
        for (int p = tid; p < V * MW; p += BS) maskA[p] = 0u;
        __syncthreads();

        const int T = nt * (nt + 1) / 2;
        for (int t = wid; t < T; t += BS / 32) {
            int ti = 0, rem = t;
            while (rem >= nt - ti) { rem -= nt - ti; ti++; }
            int tj = ti + rem;

            int j = (tj << 5) + lane;
            bool vj = j < V;
            float xj1 = 0.f, yj1 = 0.f, xj2 = 0.f, yj2 = 0.f, aj = 0.f;
            if (vj) { xj1 = bx1[j]; yj1 = by1[j]; xj2 = bx2[j]; yj2 = by2[j]; aj = sar[j]; }

            int imax = min(32, V - (ti << 5));
            for (int r = 0; r < imax; r++) {
                int i = (ti << 5) + r;
                float xi1 = bx1[i], yi1 = by1[i], xi2 = bx2[i], yi2 = by2[i];
                float ai  = sar[i];
                float xx1 = fmaxf(xi1, xj1);
                float yy1 = fmaxf(yi1, yj1);
                float xx2 = fminf(xi2, xj2);
                float yy2 = fminf(yi2, yj2);
                float ww = fmaxf(1e-28f, xx2 - xx1);
                float hh = fmaxf(1e-28f, yy2 - yy1);
                float inter = ww * hh;
                float iou = inter / (ai + aj - inter + 1e-14f);
                bool bit = vj && (j > i) && (iou > NMS_THR);
                unsigned word = __ballot_sync(0xffffffffu, bit);
                if (lane == 0) maskA[i * MW + tj] = word;
            }
        }
        __syncthreads();

        // ---- resolve: warp 0, alive bits in registers, skip dead rows ----
        if (tid < 32) {
            unsigned alive = 0;
            if (lane < MW) {
                int lo = lane << 5;
                if (lo + 32 <= V)      alive = 0xffffffffu;
                else if (lo < V)       alive = (1u << (V - lo)) - 1u;
            }
            for (int w0 = 0; (w0 << 5) < V; w0++) {
                unsigned done = 0;
                while (true) {
                    unsigned aw = __shfl_sync(0xffffffffu, alive, w0) & ~done;
                    if (!aw) break;
                    int b = __ffs(aw) - 1;
                    int i = (w0 << 5) + b;
                    done |= 1u << b;
                    unsigned row = (lane < MW) ? maskA[i * MW + lane] : 0u;
                    alive &= ~row;
                }
            }
            if (lane < 16) aliveW[lane] = (lane < MW) ? alive : 0u;
        }
        __syncthreads();

        // ---- Phase F: outputs ----
        for (int k = tid; k < KTOP; k += BS) {
            float kp = 0.f;
            if (k < V) kp = ((aliveW[k >> 5] >> (k & 31)) & 1u) ? 1.f : 0.f;
            out_scores[(size_t)cls * KTOP + k] = sc[k] * kp;
            out_keep[(size_t)cls * KTOP + k]   = kp;
        }
    } else {
        // ---- fallback (V > VMAXF): barriered greedy NMS ----
        int* kfb = (int*)maskA;
        for (int k = tid; k < V; k += BS) kfb[k] = 1;
        __syncthreads();
        for (int i = 0; i < V; i++) {
            if (kfb[i]) {
                int ia = sidx[i];
                float xi1 = g_boxes[ia * 4 + 0], yi1 = g_boxes[ia * 4 + 1];
                float xi2 = g_boxes[ia * 4 + 2], yi2 = g_boxes[ia * 4 + 3];
                float ai = (xi2 - xi1) * (yi2 - yi1);
                for (int j = i + 1 + tid; j < V; j += BS) {
                    if (kfb[j]) {
                        int ja = sidx[j];
                        float x1 = g_boxes[ja * 4 + 0], y1 = g_boxes[ja * 4 + 1];
                        float x2 = g_boxes[ja * 4 + 2], y2 = g_boxes[ja * 4 + 3];
                        float aj = (x2 - x1) * (y2 - y1);
                        float xx1 = fmaxf(xi1, x1);
                        float yy1 = fmaxf(yi1, y1);
                        float xx2 = fminf(xi2, x2);
                        float yy2 = fminf(yi2, y2);
                        float ww = fmaxf(1e-28f, xx2 - xx1);
                        float hh = fmaxf(1e-28f, yy2 - yy1);
                        float inter = ww * hh;
                        float iou = inter / (ai + aj - inter + 1e-14f);
                        if (iou > NMS_THR) kfb[j] = 0;
                    }
                }
            }
            __syncthreads();
        }
        for (int k = tid; k < KTOP; k += BS) {
            float kp = (k < V && kfb[k]) ? 1.f : 0.f;
            out_scores[(size_t)cls * KTOP + k] = sc[k] * kp;
            out_keep[(size_t)cls * KTOP + k]   = kp;
        }
    }
}

// ---------------- launch ----------------
extern "C" void kernel_launch(void* const* d_in, const int* in_sizes, int n_in,
                              void* d_out, int out_size)
{
    const float* reg  = (const float*)d_in[0];
    const float* obj  = (const float*)d_in[1];
    const float* cls  = (const float*)d_in[2];
    const float* grid = (const float*)d_in[3];
    const float* anch = (const float*)d_in[4];
    const float* strd = (const float*)d_in[5];

    int N = in_sizes[0] / 4;
    int C = in_sizes[2] / N;

    float* out = (float*)d_out;
    float* out_boxes  = out;                         // [C, K, 4]
    float* out_scores = out + (size_t)C * KTOP * 4;  // [C, K]
    float* out_keep   = out + (size_t)C * KTOP * 5;  // [C, K]

    int blocks = (N + 7) / 8;
    decode_kernel<<<blocks, 256>>>(reg, obj, cls, grid, anch, strd, N, C);
    class_kernel<<<C, BS>>>(out_boxes, out_scores, out_keep, N);
}

// round 5
// speedup vs baseline: 3.5015x; 1.2690x over previous
#include <cuda_runtime.h>
#include <math.h>
#include <float.h>

#define NMAX      26400
#define KTOP      1000
#define CONF      0.001f
#define NMS_THR   0.6f
#define CAP       2048
#define BS        512
#define MW        13          // mask words per row (covers V <= 416)
#define VMAXF     408         // fast-path limit (smem budget)
#define NCLS      128         // max classes supported by scratch

// ---------------- scratch (no allocation allowed) ----------------
__device__ float4 g_boxes4[NMAX];
__device__ float2 g_pack[NMAX];             // {score, bitcast(cls)}
__device__ int    g_ccnt[NCLS];
__device__ float2 g_clist[NCLS * CAP];      // {score, bitcast(anchor idx)}

// ---------------- kernel 0: zero per-class counters ----------------
__global__ void zero_kernel() {
    if (threadIdx.x < NCLS) g_ccnt[threadIdx.x] = 0;
}

// ---------------- kernel 1: decode, one warp per anchor ----------------
__global__ void __launch_bounds__(256) decode_kernel(
    const float* __restrict__ reg, const float* __restrict__ obj,
    const float* __restrict__ cls, const float* __restrict__ grid,
    const float* __restrict__ anch, const float* __restrict__ strd,
    int N, int C)
{
    int warp = (blockIdx.x * blockDim.x + threadIdx.x) >> 5;
    int lane = threadIdx.x & 31;
    if (warp >= N) return;

    float vmax = -FLT_MAX; int amax = 0x7fffffff;
    float v0 = 0.f, v1 = 0.f, v2 = 0.f, v3 = 0.f;
    int nq = (C + 3) >> 2;
    bool has = lane < nq;
    if (has) {
        const float4* cl4 = (const float4*)(cls + (size_t)warp * C);
        float4 q = cl4[lane];
        v0 = q.x; v1 = q.y; v2 = q.z; v3 = q.w;
        int base = lane << 2;
        vmax = v0; amax = base;
        if (v1 > vmax) { vmax = v1; amax = base + 1; }
        if (v2 > vmax) { vmax = v2; amax = base + 2; }
        if (v3 > vmax) { vmax = v3; amax = base + 3; }
    }
    for (int off = 16; off; off >>= 1) {
        float ov = __shfl_down_sync(0xffffffffu, vmax, off);
        int   oa = __shfl_down_sync(0xffffffffu, amax, off);
        if (ov > vmax || (ov == vmax && oa < amax)) { vmax = ov; amax = oa; }
    }
    vmax = __shfl_sync(0xffffffffu, vmax, 0);
    amax = __shfl_sync(0xffffffffu, amax, 0);

    float se = 0.f;
    if (has) {
        se = expf(v0 - vmax) + expf(v1 - vmax)
           + expf(v2 - vmax) + expf(v3 - vmax);
    }
    for (int off = 16; off; off >>= 1)
        se += __shfl_down_sync(0xffffffffu, se, off);

    if (lane == 0) {
        float sig_obj = 1.f / (1.f + expf(-obj[warp]));
        float score   = sig_obj * (1.f / se);
        g_pack[warp] = make_float2(score, __int_as_float(amax));

        if (score >= CONF) {
            int slot = atomicAdd(&g_ccnt[amax], 1);
            if (slot < CAP)
                g_clist[amax * CAP + slot] = make_float2(score, __int_as_float(warp));
        }

        float s  = strd[warp];
        float gx = grid[warp * 2 + 0], gy = grid[warp * 2 + 1];
        float aw = anch[warp * 2 + 0], ah = anch[warp * 2 + 1];
        float rx = reg[warp * 4 + 0], ry = reg[warp * 4 + 1];
        float rw = reg[warp * 4 + 2], rh = reg[warp * 4 + 3];

        float cx = (1.f / (1.f + expf(-rx)) + gx) * s;
        float cy = (1.f / (1.f + expf(-ry)) + gy) * s;
        float w  = expf(rw) * aw;
        float h  = expf(rh) * ah;

        float4 b;
        b.x = fminf(fmaxf((cx - 0.5f * w) / 640.0f, 0.f), 1.f);
        b.y = fminf(fmaxf((cy - 0.5f * h) / 640.0f, 0.f), 1.f);
        b.z = fminf(fmaxf((cx + 0.5f * w) / 640.0f, 0.f), 1.f);
        b.w = fminf(fmaxf((cy + 0.5f * h) / 640.0f, 0.f), 1.f);
        g_boxes4[warp] = b;
    }
}

// ---------------- kernel 2: per-class topK + fill + mask-NMS ----------------
__global__ void __launch_bounds__(BS) class_kernel(
    float* __restrict__ out_boxes, float* __restrict__ out_scores,
    float* __restrict__ out_keep, int N)
{
    __shared__ float buf[12000];
    __shared__ int s_run, s_wsum[BS / 32];
    __shared__ unsigned s_flag[16];      // per-row "has suppression bits"

    float*    sc    = buf;
    int*      sidx  = (int*)(buf + 2048);
    float*    bx1   = buf + 4096;
    float*    by1   = buf + 4608;
    float*    bx2   = buf + 5120;
    float*    by2   = buf + 5632;
    float*    sar   = buf + 6144;
    unsigned* maskA = (unsigned*)(buf + 6656);
    unsigned* aliveW = (unsigned*)(buf + 11960);

    const int cls  = blockIdx.x;
    const int tid  = threadIdx.x;
    const int wid  = tid >> 5;
    const int lane = tid & 31;

    if (tid == 0) s_run = 0;
    if (tid < 16) s_flag[tid] = 0u;

    // ---- Phase A: read this class's pre-binned candidate list ----
    int cnt = min(g_ccnt[cls], CAP);
    for (int q = tid; q < cnt; q += BS) {
        float2 p = g_clist[cls * CAP + q];
        sc[q]   = p.x;
        sidx[q] = __float_as_int(p.y);
    }

    // ---- Phase B: bitonic sort (score desc, idx asc) ----
    int M = 2; while (M < cnt) M <<= 1;
    for (int i = cnt + tid; i < M; i += BS) { sc[i] = -FLT_MAX; sidx[i] = 0x7fffffff; }
    __syncthreads();

    if (M >= 32 && M <= BS) {
        // fast path: 1 element/thread; j<=16 levels are warp-local
        for (int k = 2; k <= M; k <<= 1) {
            int j = k >> 1;
            for (; j >= 32; j >>= 1) {
                if (tid < M) {
                    int i = tid, l = i ^ j;
                    if (l > i) {
                        float si = sc[i], sl = sc[l];
                        int   ii = sidx[i], il = sidx[l];
                        bool lPrec = (sl > si) || (sl == si && il < ii);
                        bool dir   = ((i & k) == 0);
                        if (lPrec == dir) {
                            sc[i] = sl; sc[l] = si;
                            sidx[i] = il; sidx[l] = ii;
                        }
                    }
                }
                __syncthreads();
            }
            if (tid < M) {
                for (; j > 0; j >>= 1) {
                    int i = tid, l = i ^ j;
                    if (l > i) {
                        float si = sc[i], sl = sc[l];
                        int   ii = sidx[i], il = sidx[l];
                        bool lPrec = (sl > si) || (sl == si && il < ii);
                        bool dir   = ((i & k) == 0);
                        if (lPrec == dir) {
                            sc[i] = sl; sc[l] = si;
                            sidx[i] = il; sidx[l] = ii;
                        }
                    }
                    __syncwarp();
                }
            }
            __syncthreads();
        }
    } else {
        for (int k = 2; k <= M; k <<= 1) {
            for (int j = k >> 1; j > 0; j >>= 1) {
                for (int i = tid; i < M; i += BS) {
                    int l = i ^ j;
                    if (l > i) {
                        float si = sc[i], sl = sc[l];
                        int   ii = sidx[i], il = sidx[l];
                        bool lPrec = (sl > si) || (sl == si && il < ii);
                        bool dir   = ((i & k) == 0);
                        if (lPrec == dir) {
                            sc[i] = sl; sc[l] = si;
                            sidx[i] = il; sidx[l] = ii;
                        }
                    }
                }
                __syncthreads();
            }
        }
    }

    // ---- Phase C: fill remaining slots with lowest-index non-candidates ----
    const int V = min(cnt, KTOP);
    const int need = KTOP - V;
    if (need > 0) {
        for (int base = 0;; base += BS) {
            int a = base + tid;
            int flag = 0;
            if (a < N) {
                float2 p = g_pack[a];
                flag = !(__float_as_int(p.y) == cls && p.x >= CONF);
            }
            unsigned m = __ballot_sync(0xffffffffu, flag);
            int wpos = __popc(m & ((1u << lane) - 1u));
            if (lane == 0) s_wsum[wid] = __popc(m);
            __syncthreads();
            int off = 0, tot = 0;
            #pragma unroll
            for (int w = 0; w < BS / 32; w++) {
                if (w < wid) off += s_wsum[w];
                tot += s_wsum[w];
            }
            int run = s_run;
            int pos = run + off + wpos;
            if (flag && pos < need) { sc[V + pos] = -1.0f; sidx[V + pos] = a; }
            __syncthreads();
            if (tid == 0) s_run = run + tot;
            __syncthreads();
            if (run + tot >= need) break;
            if (base + BS >= N) break;
        }
    }
    __syncthreads();

    const bool fast = (V <= VMAXF);

    // ---- Phase D: gather boxes (float4) -> out_boxes; stage first V ----
    for (int k = tid; k < KTOP; k += BS) {
        int a = sidx[k];
        float4 b = g_boxes4[a];
        if (fast && k < V) {
            bx1[k] = b.x; by1[k] = b.y; bx2[k] = b.z; by2[k] = b.w;
            sar[k] = (b.z - b.x) * (b.w - b.y);
        }
        ((float4*)out_boxes)[(size_t)cls * KTOP + k] = b;
    }
    __syncthreads();

    if (fast) {
        // ---- Phase E: warp-cooperative tiled IoU mask build ----
        const int nt = (V + 31) >> 5;
        for (int p = tid; p < V * MW; p += BS) maskA[p] = 0u;
        __syncthreads();

        const int T = nt * (nt + 1) / 2;
        for (int t = wid; t < T; t += BS / 32) {
            int ti = 0, rem = t;
            while (rem >= nt - ti) { rem -= nt - ti; ti++; }
            int tj = ti + rem;

            int j = (tj << 5) + lane;
            bool vj = j < V;
            float xj1 = 0.f, yj1 = 0.f, xj2 = 0.f, yj2 = 0.f, aj = 0.f;
            if (vj) { xj1 = bx1[j]; yj1 = by1[j]; xj2 = bx2[j]; yj2 = by2[j]; aj = sar[j]; }

            int imax = min(32, V - (ti << 5));
            for (int r = 0; r < imax; r++) {
                int i = (ti << 5) + r;
                float xi1 = bx1[i], yi1 = by1[i], xi2 = bx2[i], yi2 = by2[i];
                float ai  = sar[i];
                float xx1 = fmaxf(xi1, xj1);
                float yy1 = fmaxf(yi1, yj1);
                float xx2 = fminf(xi2, xj2);
                float yy2 = fminf(yi2, yj2);
                float ww = fmaxf(1e-28f, xx2 - xx1);
                float hh = fmaxf(1e-28f, yy2 - yy1);
                float inter = ww * hh;
                float iou = inter / (ai + aj - inter + 1e-14f);
                bool bit = vj && (j > i) && (iou > NMS_THR);
                unsigned word = __ballot_sync(0xffffffffu, bit);
                if (lane == 0 && word) {
                    maskA[i * MW + tj] = word;
                    atomicOr(&s_flag[i >> 5], 1u << (i & 31));
                }
            }
        }
        __syncthreads();

        // ---- resolve: warp 0; bulk-retire rows with no suppression bits ----
        if (tid < 32) {
            unsigned alive = 0;
            if (lane < MW) {
                int lo = lane << 5;
                if (lo + 32 <= V)      alive = 0xffffffffu;
                else if (lo < V)       alive = (1u << (V - lo)) - 1u;
            }
            for (int w0 = 0; (w0 << 5) < V; w0++) {
                unsigned flagw = s_flag[w0];      // warp-uniform broadcast
                unsigned done = 0;
                while (true) {
                    unsigned aw = __shfl_sync(0xffffffffu, alive, w0) & ~done;
                    if (!aw) break;
                    unsigned actw = aw & flagw;
                    if (!actw) break;             // rest of word suppresses nothing
                    int b = __ffs(actw) - 1;
                    int i = (w0 << 5) + b;
                    done |= (aw & ((1u << b) - 1u)) | (1u << b);
                    unsigned row = (lane < MW) ? maskA[i * MW + lane] : 0u;
                    alive &= ~row;
                }
            }
            if (lane < 16) aliveW[lane] = (lane < MW) ? alive : 0u;
        }
        __syncthreads();

        // ---- Phase F: outputs ----
        for (int k = tid; k < KTOP; k += BS) {
            float kp = 0.f;
            if (k < V) kp = ((aliveW[k >> 5] >> (k & 31)) & 1u) ? 1.f : 0.f;
            out_scores[(size_t)cls * KTOP + k] = sc[k] * kp;
            out_keep[(size_t)cls * KTOP + k]   = kp;
        }
    } else {
        // ---- fallback (V > VMAXF): barriered greedy NMS ----
        int* kfb = (int*)maskA;
        for (int k = tid; k < V; k += BS) kfb[k] = 1;
        __syncthreads();
        for (int i = 0; i < V; i++) {
            if (kfb[i]) {
                float4 bi = g_boxes4[sidx[i]];
                float ai = (bi.z - bi.x) * (bi.w - bi.y);
                for (int j = i + 1 + tid; j < V; j += BS) {
                    if (kfb[j]) {
                        float4 bj = g_boxes4[sidx[j]];
                        float aj = (bj.z - bj.x) * (bj.w - bj.y);
                        float xx1 = fmaxf(bi.x, bj.x);
                        float yy1 = fmaxf(bi.y, bj.y);
                        float xx2 = fminf(bi.z, bj.z);
                        float yy2 = fminf(bi.w, bj.w);
                        float ww = fmaxf(1e-28f, xx2 - xx1);
                        float hh = fmaxf(1e-28f, yy2 - yy1);
                        float inter = ww * hh;
                        float iou = inter / (ai + aj - inter + 1e-14f);
                        if (iou > NMS_THR) kfb[j] = 0;
                    }
                }
            }
            __syncthreads();
        }
        for (int k = tid; k < KTOP; k += BS) {
            float kp = (k < V && kfb[k]) ? 1.f : 0.f;
            out_scores[(size_t)cls * KTOP + k] = sc[k] * kp;
            out_keep[(size_t)cls * KTOP + k]   = kp;
        }
    }
}

// ---------------- launch ----------------
extern "C" void kernel_launch(void* const* d_in, const int* in_sizes, int n_in,
                              void* d_out, int out_size)
{
    const float* reg  = (const float*)d_in[0];
    const float* obj  = (const float*)d_in[1];
    const float* cls  = (const float*)d_in[2];
    const float* grid = (const float*)d_in[3];
    const float* anch = (const float*)d_in[4];
    const float* strd = (const float*)d_in[5];

    int N = in_sizes[0] / 4;
    int C = in_sizes[2] / N;

    float* out = (float*)d_out;
    float* out_boxes  = out;                         // [C, K, 4]
    float* out_scores = out + (size_t)C * KTOP * 4;  // [C, K]
    float* out_keep   = out + (size_t)C * KTOP * 5;  // [C, K]

    zero_kernel<<<1, NCLS>>>();
    int blocks = (N + 7) / 8;
    decode_kernel<<<blocks, 256>>>(reg, obj, cls, grid, anch, strd, N, C);
    class_kernel<<<C, BS>>>(out_boxes, out_scores, out_keep, N);
}

// round 6
// speedup vs baseline: 4.1043x; 1.1722x over previous
#include <cuda_runtime.h>
#include <math.h>
#include <float.h>

#define NMAX      26400
#define KTOP      1000
#define CONF      0.001f
#define NMS_THR   0.6f
#define CAP       2048
#define BS        512
#define MW        13          // mask words per row (covers V <= 416)
#define VMAXF     408         // fast-path limit
#define NCLS      128
#define MSPLIT    4           // mask kernel tile splits

// ---------------- scratch (no allocation allowed) ----------------
__device__ float4  g_boxes4[NMAX];
__device__ float2  g_pack[NMAX];             // {score, bitcast(cls)}
__device__ int     g_ccnt[NCLS];
__device__ float2  g_clist[NCLS * CAP];      // {score, bitcast(anchor idx)}
__device__ float   g_ssc[NCLS * KTOP];       // sorted scores (incl. -1 fills)
__device__ int     g_sidx[NCLS * KTOP];      // sorted anchor indices
__device__ float4  g_sbox[NCLS * VMAXF];     // staged boxes (k < V)
__device__ float   g_sarA[NCLS * VMAXF];     // staged areas
__device__ int     g_V[NCLS];
__device__ unsigned g_mask[NCLS * VMAXF * MW];
__device__ unsigned g_flag[NCLS * 16];

// ---------------- kernel 1: decode, one warp per anchor ----------------
__global__ void __launch_bounds__(256) decode_kernel(
    const float* __restrict__ reg, const float* __restrict__ obj,
    const float* __restrict__ cls, const float* __restrict__ grid,
    const float* __restrict__ anch, const float* __restrict__ strd,
    int N, int C)
{
    int warp = (blockIdx.x * blockDim.x + threadIdx.x) >> 5;
    int lane = threadIdx.x & 31;
    if (warp >= N) return;

    float vmax = -FLT_MAX; int amax = 0x7fffffff;
    float v0 = 0.f, v1 = 0.f, v2 = 0.f, v3 = 0.f;
    int nq = (C + 3) >> 2;
    bool has = lane < nq;
    if (has) {
        const float4* cl4 = (const float4*)(cls + (size_t)warp * C);
        float4 q = cl4[lane];
        v0 = q.x; v1 = q.y; v2 = q.z; v3 = q.w;
        int base = lane << 2;
        vmax = v0; amax = base;
        if (v1 > vmax) { vmax = v1; amax = base + 1; }
        if (v2 > vmax) { vmax = v2; amax = base + 2; }
        if (v3 > vmax) { vmax = v3; amax = base + 3; }
    }
    for (int off = 16; off; off >>= 1) {
        float ov = __shfl_down_sync(0xffffffffu, vmax, off);
        int   oa = __shfl_down_sync(0xffffffffu, amax, off);
        if (ov > vmax || (ov == vmax && oa < amax)) { vmax = ov; amax = oa; }
    }
    vmax = __shfl_sync(0xffffffffu, vmax, 0);
    amax = __shfl_sync(0xffffffffu, amax, 0);

    float se = 0.f;
    if (has) {
        se = expf(v0 - vmax) + expf(v1 - vmax)
           + expf(v2 - vmax) + expf(v3 - vmax);
    }
    for (int off = 16; off; off >>= 1)
        se += __shfl_down_sync(0xffffffffu, se, off);

    if (lane == 0) {
        float sig_obj = 1.f / (1.f + expf(-obj[warp]));
        float score   = sig_obj * (1.f / se);
        g_pack[warp] = make_float2(score, __int_as_float(amax));

        if (score >= CONF) {
            int slot = atomicAdd(&g_ccnt[amax], 1);
            if (slot < CAP)
                g_clist[amax * CAP + slot] = make_float2(score, __int_as_float(warp));
        }

        float s  = strd[warp];
        float gx = grid[warp * 2 + 0], gy = grid[warp * 2 + 1];
        float aw = anch[warp * 2 + 0], ah = anch[warp * 2 + 1];
        float4 r = ((const float4*)reg)[warp];

        float cx = (1.f / (1.f + expf(-r.x)) + gx) * s;
        float cy = (1.f / (1.f + expf(-r.y)) + gy) * s;
        float w  = expf(r.z) * aw;
        float h  = expf(r.w) * ah;

        float4 b;
        b.x = fminf(fmaxf((cx - 0.5f * w) / 640.0f, 0.f), 1.f);
        b.y = fminf(fmaxf((cy - 0.5f * h) / 640.0f, 0.f), 1.f);
        b.z = fminf(fmaxf((cx + 0.5f * w) / 640.0f, 0.f), 1.f);
        b.w = fminf(fmaxf((cy + 0.5f * h) / 640.0f, 0.f), 1.f);
        g_boxes4[warp] = b;
    }
}

// ---------------- kernel 2: per-class sort + fill + gather ----------------
__global__ void __launch_bounds__(BS) sortfill_kernel(
    float* __restrict__ out_boxes, int N)
{
    __shared__ float sc[CAP];
    __shared__ int   sidx[CAP];
    __shared__ int   s_run, s_wsum[BS / 32];

    const int cls  = blockIdx.x;
    const int tid  = threadIdx.x;
    const int wid  = tid >> 5;
    const int lane = tid & 31;

    if (tid == 0) s_run = 0;

    int cnt = min(g_ccnt[cls], CAP);
    for (int q = tid; q < cnt; q += BS) {
        float2 p = g_clist[cls * CAP + q];
        sc[q]   = p.x;
        sidx[q] = __float_as_int(p.y);
    }
    if (tid == 0) g_ccnt[cls] = 0;   // reset for next replay

    // bitonic sort (score desc, idx asc)
    int M = 2; while (M < cnt) M <<= 1;
    for (int i = cnt + tid; i < M; i += BS) { sc[i] = -FLT_MAX; sidx[i] = 0x7fffffff; }
    __syncthreads();

    if (M >= 32 && M <= BS) {
        for (int k = 2; k <= M; k <<= 1) {
            int j = k >> 1;
            for (; j >= 32; j >>= 1) {
                if (tid < M) {
                    int i = tid, l = i ^ j;
                    if (l > i) {
                        float si = sc[i], sl = sc[l];
                        int   ii = sidx[i], il = sidx[l];
                        bool lPrec = (sl > si) || (sl == si && il < ii);
                        if (lPrec == ((i & k) == 0)) {
                            sc[i] = sl; sc[l] = si;
                            sidx[i] = il; sidx[l] = ii;
                        }
                    }
                }
                __syncthreads();
            }
            if (tid < M) {
                for (; j > 0; j >>= 1) {
                    int i = tid, l = i ^ j;
                    if (l > i) {
                        float si = sc[i], sl = sc[l];
                        int   ii = sidx[i], il = sidx[l];
                        bool lPrec = (sl > si) || (sl == si && il < ii);
                        if (lPrec == ((i & k) == 0)) {
                            sc[i] = sl; sc[l] = si;
                            sidx[i] = il; sidx[l] = ii;
                        }
                    }
                    __syncwarp();
                }
            }
            __syncthreads();
        }
    } else {
        for (int k = 2; k <= M; k <<= 1) {
            for (int j = k >> 1; j > 0; j >>= 1) {
                for (int i = tid; i < M; i += BS) {
                    int l = i ^ j;
                    if (l > i) {
                        float si = sc[i], sl = sc[l];
                        int   ii = sidx[i], il = sidx[l];
                        bool lPrec = (sl > si) || (sl == si && il < ii);
                        if (lPrec == ((i & k) == 0)) {
                            sc[i] = sl; sc[l] = si;
                            sidx[i] = il; sidx[l] = ii;
                        }
                    }
                }
                __syncthreads();
            }
        }
    }

    // fill remaining slots with lowest-index non-candidates
    const int V = min(cnt, KTOP);
    const int need = KTOP - V;
    if (need > 0) {
        for (int base = 0;; base += BS) {
            int a = base + tid;
            int flag = 0;
            if (a < N) {
                float2 p = g_pack[a];
                flag = !(__float_as_int(p.y) == cls && p.x >= CONF);
            }
            unsigned m = __ballot_sync(0xffffffffu, flag);
            int wpos = __popc(m & ((1u << lane) - 1u));
            if (lane == 0) s_wsum[wid] = __popc(m);
            __syncthreads();
            int off = 0, tot = 0;
            #pragma unroll
            for (int w = 0; w < BS / 32; w++) {
                if (w < wid) off += s_wsum[w];
                tot += s_wsum[w];
            }
            int run = s_run;
            int pos = run + off + wpos;
            if (flag && pos < need && V + pos < CAP) { sc[V + pos] = -1.0f; sidx[V + pos] = a; }
            __syncthreads();
            if (tid == 0) s_run = run + tot;
            __syncthreads();
            if (run + tot >= need) break;
            if (base + BS >= N) break;
        }
    }
    __syncthreads();

    if (tid == 0) g_V[cls] = V;

    // gather boxes -> out_boxes; stage first V; export sorted arrays
    const bool fast = (V <= VMAXF);
    for (int k = tid; k < KTOP; k += BS) {
        int a = sidx[k];
        float4 b = g_boxes4[a];
        if (fast && k < V) {
            g_sbox[cls * VMAXF + k] = b;
            g_sarA[cls * VMAXF + k] = (b.z - b.x) * (b.w - b.y);
        }
        ((float4*)out_boxes)[(size_t)cls * KTOP + k] = b;
        g_ssc[cls * KTOP + k]  = sc[k];
        g_sidx[cls * KTOP + k] = sidx[k];
    }
}

// ---------------- kernel 3: tiled IoU mask build (grid C x MSPLIT) ----------------
__global__ void __launch_bounds__(BS) mask_kernel()
{
    __shared__ float bx1[VMAXF], by1[VMAXF], bx2[VMAXF], by2[VMAXF], sar[VMAXF];

    const int cls  = blockIdx.x;
    const int tid  = threadIdx.x;
    const int wid  = tid >> 5;
    const int lane = tid & 31;

    const int V = g_V[cls];
    if (V > VMAXF) return;

    // stage boxes to smem (coalesced float4)
    for (int k = tid; k < V; k += BS) {
        float4 b = g_sbox[cls * VMAXF + k];
        bx1[k] = b.x; by1[k] = b.y; bx2[k] = b.z; by2[k] = b.w;
        sar[k] = g_sarA[cls * VMAXF + k];
    }
    __syncthreads();

    const int nt = (V + 31) >> 5;
    const int T  = nt * (nt + 1) / 2;
    unsigned* maskC = g_mask + (size_t)cls * VMAXF * MW;
    unsigned* flagC = g_flag + cls * 16;

    // this block owns tiles t with t % MSPLIT == blockIdx.y; warps stride them
    for (int t = blockIdx.y + MSPLIT * wid; t < T; t += MSPLIT * (BS / 32)) {
        int ti = 0, rem = t;
        while (rem >= nt - ti) { rem -= nt - ti; ti++; }
        int tj = ti + rem;

        int j = (tj << 5) + lane;
        bool vj = j < V;
        float xj1 = 0.f, yj1 = 0.f, xj2 = 0.f, yj2 = 0.f, aj = 0.f;
        if (vj) { xj1 = bx1[j]; yj1 = by1[j]; xj2 = bx2[j]; yj2 = by2[j]; aj = sar[j]; }

        int imax = min(32, V - (ti << 5));
        for (int r = 0; r < imax; r++) {
            int i = (ti << 5) + r;
            float xi1 = bx1[i], yi1 = by1[i], xi2 = bx2[i], yi2 = by2[i];
            float ai  = sar[i];
            float xx1 = fmaxf(xi1, xj1);
            float yy1 = fmaxf(yi1, yj1);
            float xx2 = fminf(xi2, xj2);
            float yy2 = fminf(yi2, yj2);
            float ww = fmaxf(1e-28f, xx2 - xx1);
            float hh = fmaxf(1e-28f, yy2 - yy1);
            float inter = ww * hh;
            float iou = inter / (ai + aj - inter + 1e-14f);
            bool bit = vj && (j > i) && (iou > NMS_THR);
            unsigned word = __ballot_sync(0xffffffffu, bit);
            if (lane == 0) {
                maskC[i * MW + tj] = word;      // every upper-tri word written once
                if (word) atomicOr(&flagC[i >> 5], 1u << (i & 31));
            }
        }
    }
}

// ---------------- kernel 4: resolve + outputs ----------------
__global__ void __launch_bounds__(128) resolve_out_kernel(
    float* __restrict__ out_scores, float* __restrict__ out_keep)
{
    __shared__ unsigned smask[VMAXF * MW];
    __shared__ unsigned s_flag[16];
    __shared__ unsigned aliveW[16];

    const int cls  = blockIdx.x;
    const int tid  = threadIdx.x;
    const int lane = tid & 31;
    const int V = g_V[cls];

    if (V <= VMAXF) {
        if (tid < 16) s_flag[tid] = g_flag[cls * 16 + tid];
        const unsigned* maskC = g_mask + (size_t)cls * VMAXF * MW;
        for (int p = tid; p < V * MW; p += 128) smask[p] = maskC[p];
        __syncthreads();

        if (tid < 32) {
            unsigned alive = 0;
            if (lane < MW) {
                int lo = lane << 5;
                if (lo + 32 <= V)      alive = 0xffffffffu;
                else if (lo < V)       alive = (1u << (V - lo)) - 1u;
            }
            for (int w0 = 0; (w0 << 5) < V; w0++) {
                unsigned flagw = s_flag[w0];
                unsigned done = 0;
                while (true) {
                    unsigned aw = __shfl_sync(0xffffffffu, alive, w0) & ~done;
                    if (!aw) break;
                    unsigned actw = aw & flagw;
                    if (!actw) break;
                    int b = __ffs(actw) - 1;
                    int i = (w0 << 5) + b;
                    done |= (aw & ((1u << b) - 1u)) | (1u << b);
                    // lower-tri words never written: mask by lane >= i>>5
                    unsigned row = (lane < MW && lane >= (i >> 5)) ? smask[i * MW + lane] : 0u;
                    alive &= ~row;
                }
            }
            if (lane < 16) aliveW[lane] = (lane < MW) ? alive : 0u;
        }
        __syncthreads();

        for (int k = tid; k < KTOP; k += 128) {
            float kp = 0.f;
            if (k < V) kp = ((aliveW[k >> 5] >> (k & 31)) & 1u) ? 1.f : 0.f;
            float s = g_ssc[cls * KTOP + k];
            out_scores[(size_t)cls * KTOP + k] = s * kp;
            out_keep[(size_t)cls * KTOP + k]   = kp;
        }
        __syncthreads();
        if (tid < 16) g_flag[cls * 16 + tid] = 0u;   // reset for next replay
    } else {
        // fallback: barriered greedy NMS from global data
        int* kfb = (int*)smask;
        for (int k = tid; k < V; k += 128) kfb[k] = 1;
        __syncthreads();
        for (int i = 0; i < V; i++) {
            if (kfb[i]) {
                float4 bi = g_boxes4[g_sidx[cls * KTOP + i]];
                float ai = (bi.z - bi.x) * (bi.w - bi.y);
                for (int j = i + 1 + tid; j < V; j += 128) {
                    if (kfb[j]) {
                        float4 bj = g_boxes4[g_sidx[cls * KTOP + j]];
                        float aj = (bj.z - bj.x) * (bj.w - bj.y);
                        float xx1 = fmaxf(bi.x, bj.x);
                        float yy1 = fmaxf(bi.y, bj.y);
                        float xx2 = fminf(bi.z, bj.z);
                        float yy2 = fminf(bi.w, bj.w);
                        float ww = fmaxf(1e-28f, xx2 - xx1);
                        float hh = fmaxf(1e-28f, yy2 - yy1);
                        float inter = ww * hh;
                        float iou = inter / (ai + aj - inter + 1e-14f);
                        if (iou > NMS_THR) kfb[j] = 0;
                    }
                }
            }
            __syncthreads();
        }
        for (int k = tid; k < KTOP; k += 128) {
            float kp = (k < V && kfb[k]) ? 1.f : 0.f;
            out_scores[(size_t)cls * KTOP + k] = g_ssc[cls * KTOP + k] * kp;
            out_keep[(size_t)cls * KTOP + k]   = kp;
        }
        __syncthreads();
        if (tid < 16) g_flag[cls * 16 + tid] = 0u;
    }
}

// ---------------- launch ----------------
extern "C" void kernel_launch(void* const* d_in, const int* in_sizes, int n_in,
                              void* d_out, int out_size)
{
    const float* reg  = (const float*)d_in[0];
    const float* obj  = (const float*)d_in[1];
    const float* cls  = (const float*)d_in[2];
    const float* grid = (const float*)d_in[3];
    const float* anch = (const float*)d_in[4];
    const float* strd = (const float*)d_in[5];

    int N = in_sizes[0] / 4;
    int C = in_sizes[2] / N;

    float* out = (float*)d_out;
    float* out_boxes  = out;                         // [C, K, 4]
    float* out_scores = out + (size_t)C * KTOP * 4;  // [C, K]
    float* out_keep   = out + (size_t)C * KTOP * 5;  // [C, K]

    int blocks = (N + 7) / 8;
    decode_kernel<<<blocks, 256>>>(reg, obj, cls, grid, anch, strd, N, C);
    sortfill_kernel<<<C, BS>>>(out_boxes, N);
    mask_kernel<<<dim3(C, MSPLIT), BS>>>();
    resolve_out_kernel<<<C, 128>>>(out_scores, out_keep);
}